// round 1
// baseline (speedup 1.0000x reference)
#include <cuda_runtime.h>
#include <cuda_bf16.h>
#include <math.h>

// Problem constants
#define C_DIM 2048
#define N_EXP 64
#define MAX_N 16384
#define HB 128           // tokens per histogram/rank block
#define MAX_NB (MAX_N / HB)

// ---------------- scratch (device globals; no allocation allowed) -------------
__device__ float g_logits[(size_t)MAX_N * N_EXP];
__device__ int   g_top1[MAX_N];
__device__ int   g_top2[MAX_N];
__device__ float g_p1[MAX_N];
__device__ float g_p2[MAX_N];
__device__ int   g_hist0[MAX_NB * N_EXP];
__device__ int   g_hist1[MAX_NB * N_EXP];
__device__ int   g_off0[MAX_NB * N_EXP];
__device__ int   g_off1[MAX_NB * N_EXP];

// ---------------- K1: gating GEMM  logits[n][e] = sum_c x[n][c]*w[e][c] ------
// 64 tokens x 64 experts per block, BK=64, 256 threads, 4x4 register tile.
#define TM 64
#define BK 64

__global__ __launch_bounds__(256) void k_gemm(const float* __restrict__ x,
                                              const float* __restrict__ w) {
    __shared__ float xs[TM][BK + 4];   // padded rows
    __shared__ float ws[N_EXP][BK];    // XOR-swizzled at float4 granularity

    const int tid = threadIdx.x;
    const int block_t0 = blockIdx.x * TM;
    const int tg = tid >> 4;          // 0..15 -> tokens tg*4..+3
    const int eg = tid & 15;          // 0..15 -> experts eg*4..+3
    const int t0 = tg << 2;
    const int e0 = eg << 2;

    float acc[4][4];
#pragma unroll
    for (int i = 0; i < 4; i++)
#pragma unroll
        for (int j = 0; j < 4; j++) acc[i][j] = 0.0f;

    for (int k0 = 0; k0 < C_DIM; k0 += BK) {
        // cooperative tile load: 64x64 floats each = 1024 float4, 256 thr -> 4 each
#pragma unroll
        for (int l = 0; l < 4; l++) {
            int idx = tid + l * 256;          // 0..1023
            int r   = idx >> 4;               // row 0..63
            int c4  = idx & 15;               // float4 column 0..15
            float4 xv = *(const float4*)&x[(size_t)(block_t0 + r) * C_DIM + k0 + (c4 << 2)];
            *(float4*)&xs[r][c4 << 2] = xv;
            float4 wv = *(const float4*)&w[(size_t)r * C_DIM + k0 + (c4 << 2)];
            int sc4 = c4 ^ ((r >> 2) & 7);    // bank swizzle
            *(float4*)&ws[r][sc4 << 2] = wv;
        }
        __syncthreads();

#pragma unroll 4
        for (int kk = 0; kk < BK; kk += 4) {
            float4 xv[4], wv[4];
#pragma unroll
            for (int i = 0; i < 4; i++)
                xv[i] = *(const float4*)&xs[t0 + i][kk];
#pragma unroll
            for (int j = 0; j < 4; j++) {
                int e = e0 + j;
                int sc4 = (kk >> 2) ^ ((e >> 2) & 7);
                wv[j] = *(const float4*)&ws[e][sc4 << 2];
            }
#pragma unroll
            for (int i = 0; i < 4; i++) {
#pragma unroll
                for (int j = 0; j < 4; j++) {
                    acc[i][j] += xv[i].x * wv[j].x;
                    acc[i][j] += xv[i].y * wv[j].y;
                    acc[i][j] += xv[i].z * wv[j].z;
                    acc[i][j] += xv[i].w * wv[j].w;
                }
            }
        }
        __syncthreads();
    }

#pragma unroll
    for (int i = 0; i < 4; i++) {
        size_t row = (size_t)(block_t0 + t0 + i) * N_EXP;
#pragma unroll
        for (int j = 0; j < 4; j++)
            g_logits[row + e0 + j] = acc[i][j];
    }
}

// ---------------- K2: top-2 + softmax ----------------------------------------
__global__ void k_topk(int N) {
    int n = blockIdx.x * blockDim.x + threadIdx.x;
    if (n >= N) return;
    const float* row = g_logits + (size_t)n * N_EXP;
    float b1 = -INFINITY, b2 = -INFINITY;
    int i1 = 0, i2 = 0;
#pragma unroll 8
    for (int e = 0; e < N_EXP; e++) {
        float v = row[e];
        if (v > b1) { b2 = b1; i2 = i1; b1 = v; i1 = e; }
        else if (v > b2) { b2 = v; i2 = e; }
    }
    float e2 = expf(b2 - b1);        // <= 1
    float inv = 1.0f / (1.0f + e2);
    g_top1[n] = i1; g_top2[n] = i2;
    g_p1[n] = inv;
    g_p2[n] = e2 * inv;
}

// ---------------- K3: per-block expert histograms ----------------------------
__global__ void k_hist() {
    __shared__ int h0[N_EXP], h1[N_EXP];
    int tid = threadIdx.x;
    int b = blockIdx.x;
    if (tid < N_EXP) { h0[tid] = 0; h1[tid] = 0; }
    __syncthreads();
    int n = b * HB + tid;
    atomicAdd(&h0[g_top1[n]], 1);
    atomicAdd(&h1[g_top2[n]], 1);
    __syncthreads();
    if (tid < N_EXP) {
        g_hist0[b * N_EXP + tid] = h0[tid];
        g_hist1[b * N_EXP + tid] = h1[tid];
    }
}

// ---------------- K4: exclusive prefix over blocks per expert ----------------
// rank for (n, k=0) = #{n'<n : top1==e};  (n, k=1) = total0[e] + #{n'<n : top2==e}
__global__ void k_prefix(int NB) {
    int e = threadIdx.x;
    if (e >= N_EXP) return;
    int run = 0;
    for (int b = 0; b < NB; b++) {
        g_off0[b * N_EXP + e] = run;
        run += g_hist0[b * N_EXP + e];
    }
    int run1 = run;                    // total over all k=0 assignments
    for (int b = 0; b < NB; b++) {
        g_off1[b * N_EXP + e] = run1;
        run1 += g_hist1[b * N_EXP + e];
    }
}

// ---------------- K5: ranks, capacity mask, all outputs ----------------------
__global__ void k_final(int N, int cap, float* __restrict__ out, long out_elems) {
    __shared__ int s1[HB], s2[HB], r0[HB], r1[HB];
    __shared__ float sp1[HB], sp2[HB];
    int tid = threadIdx.x;
    int b = blockIdx.x;
    int n = b * HB + tid;

    s1[tid] = g_top1[n];
    s2[tid] = g_top2[n];
    sp1[tid] = g_p1[n];
    sp2[tid] = g_p2[n];
    __syncthreads();

    if (tid < N_EXP) {
        int e = tid;
        int c = g_off0[b * N_EXP + e];
        for (int i = 0; i < HB; i++)
            if (s1[i] == e) r0[i] = c++;
        c = g_off1[b * N_EXP + e];
        for (int i = 0; i < HB; i++)
            if (s2[i] == e) r1[i] = c++;
    }
    __syncthreads();

    // output layout (float32 elements):
    //   [0, N*128)              final_mask  [N,2,64]
    //   [N*128, N*130)          router_probs_masked [N,2]
    //   [N*130, N*132)          top_k_indices [N,2]
    //   [N*132, N*134)          final_rank [N,2]
    //   [N*134]                 exp_capacity
    const size_t off_probs = (size_t)N * 128;
    const size_t off_idx   = off_probs + (size_t)N * 2;
    const size_t off_rank  = off_idx + (size_t)N * 2;
    const size_t off_cap   = off_rank + (size_t)N * 2;

    int t1 = s1[tid], t2 = s2[tid];
    int rr0 = r0[tid], rr1 = r1[tid];
    bool k0 = rr0 < cap, k1 = rr1 < cap;

    size_t p;
    p = off_idx + (size_t)n * 2;
    if (p + 1 < (size_t)out_elems) { out[p] = (float)t1; out[p + 1] = (float)t2; }
    p = off_rank + (size_t)n * 2;
    if (p + 1 < (size_t)out_elems) { out[p] = (float)rr0; out[p + 1] = (float)rr1; }
    p = off_probs + (size_t)n * 2;
    if (p + 1 < (size_t)out_elems) {
        out[p]     = k0 ? sp1[tid] : 0.0f;
        out[p + 1] = k1 ? sp2[tid] : 0.0f;
    }
    if (b == 0 && tid == 0 && off_cap < (size_t)out_elems) out[off_cap] = (float)cap;

    // mask slab: coalesced — for each token row i, thread `tid` writes column tid
    for (int i = 0; i < HB; i++) {
        size_t tn = (size_t)(b * HB + i);
        size_t base = tn * 128;
        float v;
        if (tid < 64)
            v = (s1[i] == tid && r0[i] < cap) ? 1.0f : 0.0f;
        else
            v = (s2[i] == (tid - 64) && r1[i] < cap) ? 1.0f : 0.0f;
        size_t pos = base + tid;
        if (pos < (size_t)out_elems) out[pos] = v;
    }
}

// ---------------- launch ------------------------------------------------------
extern "C" void kernel_launch(void* const* d_in, const int* in_sizes, int n_in,
                              void* d_out, int out_size) {
    const float* x = (const float*)d_in[0];
    const float* w = (const float*)d_in[1];
    int N = in_sizes[0] / C_DIM;              // 16384
    if (N > MAX_N) N = MAX_N;

    // exp_capacity = max(int(TOP_K * EVAL_CAPACITY * N / N_EXP), 4)
    int cap = (int)((2.0 * 2.0 * (double)N) / 64.0);
    if (cap < 4) cap = 4;

    int NB = N / HB;

    k_gemm<<<N / TM, 256>>>(x, w);
    k_topk<<<(N + 255) / 256, 256>>>(N);
    k_hist<<<NB, HB>>>();
    k_prefix<<<1, N_EXP>>>(NB);
    k_final<<<NB, HB>>>(N, cap, (float*)d_out, (long)out_size);
}